// round 7
// baseline (speedup 1.0000x reference)
#include <cuda_runtime.h>
#include <cuda_bf16.h>

#define FULL 0xFFFFFFFFu

constexpr int BATCH = 4096;
constexpr int DIM   = 32;
constexpr int N_MEM = 32;
constexpr int N_REL = 64;
constexpr int NCOL  = N_REL * DIM;   // 2048

// Static scratch (no runtime allocation allowed).
// g_U is stored in a FRAGMENT-NATIVE permuted layout (see maps below).
__device__ __nv_bfloat16  g_U[BATCH * NCOL];          // 16 MB bf16, permuted
__device__ float          g_item[BATCH * DIM];
__device__ __nv_bfloat16  g_item_bf[BATCH * DIM];
__device__ __nv_bfloat16  g_Bt[NCOL * DIM];           // Bt[n][k]=R_r[k][e], n=r*32+e
__device__ float          g_Wt[DIM * DIM];
__device__ float          g_y[BATCH * DIM];

__device__ __forceinline__ float bf_lo(unsigned u) { return __uint_as_float(u << 16); }
__device__ __forceinline__ float bf_hi(unsigned u) { return __uint_as_float(u & 0xFFFF0000u); }

// ---------------------------------------------------------------- prep
__global__ void prep_kernel(const int* __restrict__ items,
                            const float* __restrict__ entity,
                            const float* __restrict__ relation,
                            const float* __restrict__ W) {
    const int i = blockIdx.x * blockDim.x + threadIdx.x;
    if (i < BATCH * DIM) {
        const int b = i >> 5, e = i & 31;
        const float v = entity[items[b] * DIM + e];
        g_item[i] = v;
        g_item_bf[i] = __float2bfloat16(v);
    }
    if (i < NCOL * DIM) {
        const int n = i >> 5, k = i & 31;
        const int r = n >> 5, e = n & 31;
        g_Bt[i] = __float2bfloat16(relation[r * 1024 + k * DIM + e]);
    }
    if (i < DIM * DIM) {
        const int d = i >> 5, e = i & 31;
        g_Wt[e * DIM + d] = W[i];
    }
}

// ---------------------------------------------------------------- GEMM
// U(4096x2048 bf16) = A(4096x32 bf16) * B(32x2048), B given as Bt[n][k].
//
// Permuted U layout (bytes), block tile (mt, nt) with GM=128, GN=64:
//   blockBase = (mt*32 + nt) * 16384
//   +  warp*2048  (warp owns rows warp*16..+15 of the m-tile)
//   +  j*256      (j = 8-col group within the n-tile)
//   +  hi*128     (hi=0: frag rows 0-7 / c01; hi=1: rows 8-15 / c23)
//   +  (row8*4 + colpair)*4    -- 4 B per bf16x2 (two adjacent cols)
__device__ __forceinline__ void mma16816(float c[4], const unsigned* a,
                                         const unsigned* b) {
    asm volatile(
        "mma.sync.aligned.m16n8k16.row.col.f32.bf16.bf16.f32 "
        "{%0,%1,%2,%3}, {%4,%5,%6,%7}, {%8,%9}, {%0,%1,%2,%3};\n"
        : "+f"(c[0]), "+f"(c[1]), "+f"(c[2]), "+f"(c[3])
        : "r"(a[0]), "r"(a[1]), "r"(a[2]), "r"(a[3]),
          "r"(b[0]), "r"(b[1]));
}

__device__ __forceinline__ void ldsm_x4(unsigned& r0, unsigned& r1,
                                        unsigned& r2, unsigned& r3,
                                        unsigned addr) {
    asm volatile(
        "ldmatrix.sync.aligned.m8n8.x4.shared.b16 {%0,%1,%2,%3}, [%4];\n"
        : "=r"(r0), "=r"(r1), "=r"(r2), "=r"(r3) : "r"(addr));
}

constexpr int GM = 128, GN = 64;
constexpr int ASTR = 80;    // bytes per sA row (64 payload + 16 pad)
constexpr int BSTR = 80;

__global__ void __launch_bounds__(256) gemm_kernel() {
    __shared__ __align__(16) char sA[GM * ASTR];   // 10 KB
    __shared__ __align__(16) char sB[GN * BSTR];   // 5 KB

    const int tid  = threadIdx.x;
    const int lane = tid & 31;
    const int warp = tid >> 5;
    const int m0 = blockIdx.y * GM;
    const int n0 = blockIdx.x * GN;

    // ---- stage A (128 x 64 B) and B (64 x 64 B), coalesced ----
    {
        const int row = tid >> 1, half = tid & 1;
        const uint4* src = (const uint4*)(g_item_bf + (m0 + row) * DIM) + half * 2;
        uint4* dst = (uint4*)(sA + row * ASTR) + half * 2;
        dst[0] = src[0];
        dst[1] = src[1];
    }
    if (tid < 128) {
        const int row = tid >> 1, half = tid & 1;
        const uint4* src = (const uint4*)(g_Bt + (n0 + row) * DIM) + half * 2;
        uint4* dst = (uint4*)(sB + row * BSTR) + half * 2;
        dst[0] = src[0];
        dst[1] = src[1];
    }
    __syncthreads();

    const unsigned sA32 = (unsigned)__cvta_generic_to_shared(sA);
    const unsigned sB32 = (unsigned)__cvta_generic_to_shared(sB);

    // ---- A fragments (16 rows per warp, K=32) ----
    const int mat = lane >> 3, mrow = lane & 7;
    unsigned a[8];
    {
        const unsigned rowa = warp * 16 + mrow + (mat & 1) * 8;
        const unsigned coff = (mat >> 1) * 16;
        ldsm_x4(a[0], a[1], a[2], a[3], sA32 + rowa * ASTR + coff);
        ldsm_x4(a[4], a[5], a[6], a[7], sA32 + rowa * ASTR + 32 + coff);
    }

    // ---- j-steps: B frag + 2 MMAs + direct fragment-native STG ----
    const unsigned baddr = sB32 + (lane & 7) * BSTR + (lane >> 3) * 16;
    char* __restrict__ outBase = (char*)g_U
        + (size_t)(blockIdx.y * 32 + blockIdx.x) * 16384
        + warp * 2048 + lane * 4;

    #pragma unroll
    for (int j = 0; j < 8; ++j) {
        unsigned b[4];
        ldsm_x4(b[0], b[1], b[2], b[3], baddr + j * 8 * BSTR);
        float c[4] = {0.f, 0.f, 0.f, 0.f};
        mma16816(c, a, b);
        mma16816(c, a + 4, b + 2);

        const __nv_bfloat162 p01 = __float22bfloat162_rn(make_float2(c[0], c[1]));
        const __nv_bfloat162 p23 = __float22bfloat162_rn(make_float2(c[2], c[3]));
        *(__nv_bfloat162*)(outBase + j * 256)       = p01;
        *(__nv_bfloat162*)(outBase + j * 256 + 128) = p23;
    }
}

// ---------------------------------------------------------------- attention
// 1 batch element per 64-thread block (2 warps, each owns 16 memories).
__global__ void __launch_bounds__(64) attn_kernel(
    const int* __restrict__ mem_h,
    const int* __restrict__ mem_r,
    const int* __restrict__ mem_t,
    const int* __restrict__ users,
    const float* __restrict__ entity,
    const float* __restrict__ user_table,
    float* __restrict__ out,
    int hop, int last)
{
    __shared__ float P[N_MEM * 9];
    __shared__ float O[2][DIM];

    const int lane = threadIdx.x & 31;
    const int half = threadIdx.x >> 5;
    const int b = blockIdx.x;

    const int base = hop * BATCH * N_MEM + b * N_MEM;
    const int hidx = mem_h[base + lane];   // lane m holds memory m's indices
    const int ridx = mem_r[base + lane];
    const int tidx = mem_t[base + lane];

    const float item = g_item[b * DIM + lane];

    // ---- partial dots into P: this warp's 16 memories, 4 at a time ----
    const int mq = lane >> 3;          // which of 4 memories this iter
    const int c  = lane & 7;           // e-chunk: e = 4c..4c+3
    // inverse of the GEMM's fragment-native layout (warp-uniform except c):
    const char* __restrict__ Ub = (const char*)g_U
        + (size_t)(b >> 7) * 524288          // m-tile
        + ((b >> 4) & 7) * 2048              // warp within tile
        + ((b >> 3) & 1) * 128               // hi (frag row 0-7 vs 8-15)
        + (b & 7) * 16                       // row8
        + ((c >> 1) & 3) * 256               // j within n-tile (low bits)
        + (c & 1) * 8;                       // colpair parity

    #pragma unroll
    for (int it = 0; it < 4; ++it) {
        const int m = half * 16 + it * 4 + mq;
        const int r_i = __shfl_sync(FULL, ridx, m);
        const int h_i = __shfl_sync(FULL, hidx, m);
        const uint2 uu = *(const uint2*)(Ub + (r_i >> 1) * 16384 + (r_i & 1) * 1024);
        const float4 h4 = *(const float4*)(entity + h_i * DIM + 4 * c);
        P[m * 9 + c] = bf_lo(uu.x) * h4.x + bf_hi(uu.x) * h4.y +
                       bf_lo(uu.y) * h4.z + bf_hi(uu.y) * h4.w;
    }
    __syncthreads();

    // ---- logit[m] (lane m) = sum of 8 partials; both warps redundant ----
    float logit = 0.f;
    #pragma unroll
    for (int j = 0; j < 8; ++j) logit += P[lane * 9 + j];

    // ---- softmax ----
    float mx = logit;
    #pragma unroll
    for (int off = 16; off; off >>= 1)
        mx = fmaxf(mx, __shfl_xor_sync(FULL, mx, off));
    const float ex = __expf(logit - mx);
    float denom = ex;
    #pragma unroll
    for (int off = 16; off; off >>= 1)
        denom += __shfl_xor_sync(FULL, denom, off);
    const float prob = ex / denom;

    // ---- o[d]: this warp's 16 memories (lane = d) ----
    float oh = 0.f;
    #pragma unroll 4
    for (int mm = 0; mm < 16; ++mm) {
        const int m = half * 16 + mm;
        const int t_i = __shfl_sync(FULL, tidx, m);
        const float p = __shfl_sync(FULL, prob, m);
        oh = fmaf(p, entity[t_i * DIM + lane], oh);
    }
    O[half][lane] = oh;
    __syncthreads();
    const float o = O[0][lane] + O[1][lane];

    // ---- item' = (item + o) @ W^T ----
    const float tmp = item + o;
    float itn = 0.f;
    #pragma unroll
    for (int e = 0; e < DIM; ++e)
        itn = fmaf(__shfl_sync(FULL, tmp, e), g_Wt[e * DIM + lane], itn);

    if (!last) {
        if (half == 0) {
            g_item[b * DIM + lane] = itn;
            g_item_bf[b * DIM + lane] = __float2bfloat16(itn);
            g_y[b * DIM + lane] = o;
        }
    } else if (half == 0) {
        const float y = g_y[b * DIM + lane] + o
                      + user_table[users[b] * DIM + lane];
        float s = itn * y;
        #pragma unroll
        for (int off = 16; off; off >>= 1)
            s += __shfl_xor_sync(FULL, s, off);
        if (lane == 0)
            out[b] = 1.f / (1.f + __expf(-s));
    }
}

// ---------------------------------------------------------------- launch
extern "C" void kernel_launch(void* const* d_in, const int* in_sizes, int n_in,
                              void* d_out, int out_size) {
    const int*   items     = (const int*)d_in[0];
    const int*   mem_h     = (const int*)d_in[2];
    const int*   mem_r     = (const int*)d_in[3];
    const int*   mem_t     = (const int*)d_in[4];
    const int*   users     = (const int*)d_in[5];
    const float* entity    = (const float*)d_in[6];
    const float* relation  = (const float*)d_in[7];
    const float* user_tab  = (const float*)d_in[8];
    const float* W         = (const float*)d_in[9];
    float* out = (float*)d_out;

    prep_kernel<<<(BATCH * DIM + 255) / 256, 256>>>(items, entity, relation, W);

    const dim3 ggrid(NCOL / GN, BATCH / GM);   // 32 x 32
    gemm_kernel<<<ggrid, 256>>>();
    attn_kernel<<<BATCH, 64>>>(mem_h, mem_r, mem_t, users,
                               entity, user_tab, out, 0, 0);
    gemm_kernel<<<ggrid, 256>>>();
    attn_kernel<<<BATCH, 64>>>(mem_h, mem_r, mem_t, users,
                               entity, user_tab, out, 1, 1);
}

// round 8
// speedup vs baseline: 1.1873x; 1.1873x over previous
#include <cuda_runtime.h>
#include <cuda_bf16.h>

#define FULL 0xFFFFFFFFu

constexpr int BATCH = 4096;
constexpr int DIM   = 32;
constexpr int N_MEM = 32;
constexpr int N_REL = 64;
constexpr int NCOL  = N_REL * DIM;   // 2048

// Static scratch (no runtime allocation allowed).
__device__ __nv_bfloat16  g_U[BATCH * NCOL];        // 16 MB bf16, LINEAR [b][n]
__device__ float          g_item[BATCH * DIM];
__device__ unsigned       g_Afrag[(BATCH / 16) * 2 * 32 * 4];   // A MMA frags
__device__ unsigned       g_Bfrag[(NCOL / 64) * 8 * 32 * 4];    // B MMA frags
__device__ float          g_Wt[DIM * DIM];
__device__ float          g_y[BATCH * DIM];

__device__ __forceinline__ float bf_lo(unsigned u) { return __uint_as_float(u << 16); }
__device__ __forceinline__ float bf_hi(unsigned u) { return __uint_as_float(u & 0xFFFF0000u); }

// Scatter one bf16 of the item vector into A-fragment layout.
// A frag (m16n8k16 row-major), warp-uniform per 16-row group mg:
//   uint4[ (mg*2+h)*32 + l ], elements x,y,z,w; h = k-half (e>=16)
__device__ __forceinline__ void afrag_store(int b, int e, float v) {
    const int mg = b >> 4, r = b & 15;
    const int h  = e >> 4, k = e & 15, kp = k >> 1;
    const int sel = ((r >> 3) & 1) + 2 * (kp >> 2);
    const int l   = (r & 7) * 4 + (kp & 3);
    const int idx = ((mg * 2 + h) * 32 + l) * 4 + sel;
    ((__nv_bfloat16*)g_Afrag)[idx * 2 + (k & 1)] = __float2bfloat16(v);
}

// ---------------------------------------------------------------- prep
__global__ void prep_kernel(const int* __restrict__ items,
                            const float* __restrict__ entity,
                            const float* __restrict__ relation,
                            const float* __restrict__ W) {
    const int i = blockIdx.x * blockDim.x + threadIdx.x;
    if (i < BATCH * DIM) {
        const int b = i >> 5, e = i & 31;
        const float v = entity[items[b] * DIM + e];
        g_item[i] = v;
        afrag_store(b, e, v);
    }
    // B fragments: one u32 per thread. Bt[n][k] = relation[r*1024 + k*32 + e]
    if (i < (NCOL / 64) * 8 * 32 * 4) {
        const int nt = i >> 10, j = (i >> 7) & 7, l = (i >> 2) & 31, s = i & 3;
        const int n = nt * 64 + 8 * j + (l >> 2);
        const int r = n >> 5, e = n & 31;
        const int k0 = 2 * (l & 3) + 8 * s;
        const __nv_bfloat16 lo = __float2bfloat16(relation[r * 1024 + k0 * DIM + e]);
        const __nv_bfloat16 hi = __float2bfloat16(relation[r * 1024 + (k0 + 1) * DIM + e]);
        g_Bfrag[i] = ((unsigned)__bfloat16_as_ushort(hi) << 16) |
                     (unsigned)__bfloat16_as_ushort(lo);
    }
    if (i < DIM * DIM) {
        const int d = i >> 5, e = i & 31;
        g_Wt[e * DIM + d] = W[i];
    }
}

// ---------------------------------------------------------------- GEMM
__device__ __forceinline__ void mma16816(float c[4], const unsigned* a,
                                         unsigned b0, unsigned b1) {
    asm volatile(
        "mma.sync.aligned.m16n8k16.row.col.f32.bf16.bf16.f32 "
        "{%0,%1,%2,%3}, {%4,%5,%6,%7}, {%8,%9}, {%0,%1,%2,%3};\n"
        : "+f"(c[0]), "+f"(c[1]), "+f"(c[2]), "+f"(c[3])
        : "r"(a[0]), "r"(a[1]), "r"(a[2]), "r"(a[3]), "r"(b0), "r"(b1));
}

constexpr int GM = 128, GN = 64;
constexpr int OSTR = 144;   // bytes per sO row (128 payload + 16 pad)

__global__ void __launch_bounds__(256) gemm_kernel() {
    __shared__ __align__(16) char sO[8][16 * OSTR];   // per-warp slice, 18 KB

    const int lane = threadIdx.x & 31;
    const int warp = threadIdx.x >> 5;
    const int m0 = blockIdx.y * GM;
    const int n0 = blockIdx.x * GN;
    const int mg = blockIdx.y * 8 + warp;     // 16-row group
    const int nt = blockIdx.x;

    // ---- A fragments: 2 coalesced LDG.128 ----
    const uint4* __restrict__ Af = (const uint4*)g_Afrag;
    const uint4 qa0 = Af[(mg * 2 + 0) * 32 + lane];   // k 0-15
    const uint4 qa1 = Af[(mg * 2 + 1) * 32 + lane];   // k 16-31

    const uint4* __restrict__ Bf = (const uint4*)g_Bfrag;
    char* __restrict__ so = sO[warp];

    #pragma unroll
    for (int j = 0; j < 8; ++j) {
        const uint4 qb = Bf[(nt * 8 + j) * 32 + lane];
        float c[4] = {0.f, 0.f, 0.f, 0.f};
        mma16816(c, (const unsigned*)&qa0, qb.x, qb.y);   // k 0-15
        mma16816(c, (const unsigned*)&qa1, qb.z, qb.w);   // k 16-31

        const __nv_bfloat162 p01 = __float22bfloat162_rn(make_float2(c[0], c[1]));
        const __nv_bfloat162 p23 = __float22bfloat162_rn(make_float2(c[2], c[3]));
        const int row  = lane >> 2;
        const int colb = (8 * j + 2 * (lane & 3)) * 2;
        *(__nv_bfloat162*)(so + row * OSTR + colb)       = p01;
        *(__nv_bfloat162*)(so + (row + 8) * OSTR + colb) = p23;
    }
    __syncwarp();

    // ---- copy own 16x128B slice to linear g_U, coalesced ----
    char* __restrict__ gU = (char*)g_U;
    #pragma unroll
    for (int i = 0; i < 4; ++i) {
        const int idx = lane + 32 * i;          // 128 uint4
        const int row = idx >> 3, ch = idx & 7;
        const uint4 v = *(const uint4*)(so + row * OSTR + ch * 16);
        *(uint4*)(gU + ((size_t)(m0 + warp * 16 + row) * NCOL + n0) * 2 + ch * 16) = v;
    }
}

// ---------------------------------------------------------------- attention
constexpr int AW = 8;   // warps (batch elems) per attn block

__global__ void __launch_bounds__(256) attn_kernel(
    const int* __restrict__ mem_h,
    const int* __restrict__ mem_r,
    const int* __restrict__ mem_t,
    const int* __restrict__ users,
    const float* __restrict__ entity,
    const float* __restrict__ user_table,
    float* __restrict__ out,
    int hop, int last)
{
    __shared__ float P[AW][N_MEM * 9];

    const int lane = threadIdx.x & 31;
    const int warp = threadIdx.x >> 5;
    const int b = blockIdx.x * AW + warp;
    float* __restrict__ Pw = P[warp];

    const int base = hop * BATCH * N_MEM + b * N_MEM;
    const int hidx = mem_h[base + lane];
    const int ridx = mem_r[base + lane];
    const int tidx = mem_t[base + lane];

    const float item = g_item[b * DIM + lane];

    // ---- partial dots: 4 memories/iter, 8 lanes each (e = 4c..4c+3) ----
    const int mq = lane >> 3;
    const int c  = lane & 7;
    const __nv_bfloat16* __restrict__ Ub = g_U + (size_t)b * NCOL;

    #pragma unroll
    for (int it = 0; it < 8; ++it) {
        const int m = it * 4 + mq;
        const int r_i = __shfl_sync(FULL, ridx, m);
        const int h_i = __shfl_sync(FULL, hidx, m);
        const uint2 uu = *(const uint2*)(Ub + r_i * DIM + 4 * c);  // 4 bf16
        const float4 h4 = *(const float4*)(entity + h_i * DIM + 4 * c);
        Pw[m * 9 + c] = bf_lo(uu.x) * h4.x + bf_hi(uu.x) * h4.y +
                        bf_lo(uu.y) * h4.z + bf_hi(uu.y) * h4.w;
    }
    __syncwarp();

    // ---- logit[m] (lane m) = sum of 8 partials ----
    float logit = 0.f;
    #pragma unroll
    for (int j = 0; j < 8; ++j) logit += Pw[lane * 9 + j];

    // ---- softmax ----
    float mx = logit;
    #pragma unroll
    for (int off = 16; off; off >>= 1)
        mx = fmaxf(mx, __shfl_xor_sync(FULL, mx, off));
    const float ex = __expf(logit - mx);
    float denom = ex;
    #pragma unroll
    for (int off = 16; off; off >>= 1)
        denom += __shfl_xor_sync(FULL, denom, off);
    const float prob = ex / denom;

    // ---- o[d] = sum_m prob[m] * t_m[d] ----
    float o = 0.f;
    #pragma unroll 4
    for (int m = 0; m < N_MEM; ++m) {
        const int t_i = __shfl_sync(FULL, tidx, m);
        const float p = __shfl_sync(FULL, prob, m);
        o = fmaf(p, entity[t_i * DIM + lane], o);
    }

    // ---- item' = (item + o) @ W^T ----
    const float tmp = item + o;
    float itn = 0.f;
    #pragma unroll
    for (int e = 0; e < DIM; ++e)
        itn = fmaf(__shfl_sync(FULL, tmp, e), g_Wt[e * DIM + lane], itn);

    if (!last) {
        g_item[b * DIM + lane] = itn;
        g_y[b * DIM + lane] = o;
        afrag_store(b, lane, itn);        // next GEMM's A fragment
    } else {
        const float y = g_y[b * DIM + lane] + o
                      + user_table[users[b] * DIM + lane];
        float s = itn * y;
        #pragma unroll
        for (int off = 16; off; off >>= 1)
            s += __shfl_xor_sync(FULL, s, off);
        if (lane == 0)
            out[b] = 1.f / (1.f + __expf(-s));
    }
}

// ---------------------------------------------------------------- launch
extern "C" void kernel_launch(void* const* d_in, const int* in_sizes, int n_in,
                              void* d_out, int out_size) {
    const int*   items     = (const int*)d_in[0];
    const int*   mem_h     = (const int*)d_in[2];
    const int*   mem_r     = (const int*)d_in[3];
    const int*   mem_t     = (const int*)d_in[4];
    const int*   users     = (const int*)d_in[5];
    const float* entity    = (const float*)d_in[6];
    const float* relation  = (const float*)d_in[7];
    const float* user_tab  = (const float*)d_in[8];
    const float* W         = (const float*)d_in[9];
    float* out = (float*)d_out;

    prep_kernel<<<(BATCH * DIM + 255) / 256, 256>>>(items, entity, relation, W);

    const dim3 ggrid(NCOL / GN, BATCH / GM);   // 32 x 32
    gemm_kernel<<<ggrid, 256>>>();
    attn_kernel<<<BATCH / AW, 256>>>(mem_h, mem_r, mem_t, users,
                                     entity, user_tab, out, 0, 0);
    gemm_kernel<<<ggrid, 256>>>();
    attn_kernel<<<BATCH / AW, 256>>>(mem_h, mem_r, mem_t, users,
                                     entity, user_tab, out, 1, 1);
}